// round 6
// baseline (speedup 1.0000x reference)
#include <cuda_runtime.h>
#include <cstdint>

// StatsQuantizer 4-bit fake-quant, 8192x8192 fp32.
//   s   = 2 * mean(|w_row|)
//   c   = clamp(w/s, -clip/2, clip/2 - 1e-6)
//   out = s * ((rint(c*8 - 0.5) + 0.5) / 8)
//
// Persistent double-buffered TMA pipeline: 444 CTAs (3/SM), each loops
// over ~18 rows. TMA load for row i+1 is issued BEFORE computing row i,
// so the DRAM read stream never pauses at barriers/compute. Stores are
// streaming STG.128. 2 x 32KB smem buffers per CTA.

#define ROWS 8192
#define COLS 8192
#define TPB  256
#define ROW_BYTES (COLS * 4)        // 32768
#define V4 (COLS / 4 / TPB)         // 8 float4 per thread
#define GRID 444                    // 148 SMs x 3 CTAs

// dynamic smem layout:
//   [0, 32768)          buf0
//   [32768, 65536)      buf1
//   [65536, 65552)      mbar[2]
//   [65552, 65584)      warp_sums[8]
//   [65584, 65588)      s_scale
#define SMEM_BYTES 65664

__device__ __forceinline__ void mbar_wait(uint32_t mbar_addr, uint32_t parity) {
    uint32_t done;
    asm volatile(
        "{\n\t.reg .pred p;\n\t"
        "mbarrier.try_wait.parity.acquire.cta.shared::cta.b64 p, [%1], %2;\n\t"
        "selp.b32 %0, 1, 0, p;\n\t}"
        : "=r"(done) : "r"(mbar_addr), "r"(parity) : "memory");
    if (!done) {
        asm volatile(
            "{\n\t.reg .pred P1;\n\t"
            "WAIT_LOOP_%=:\n\t"
            "mbarrier.try_wait.parity.acquire.cta.shared::cta.b64 P1, [%0], %1, 0x989680;\n\t"
            "@P1 bra.uni WAIT_DONE_%=;\n\t"
            "bra.uni WAIT_LOOP_%=;\n\t"
            "WAIT_DONE_%=:\n\t}"
            :: "r"(mbar_addr), "r"(parity) : "memory");
    }
}

__device__ __forceinline__ void tma_load_row(uint32_t dst_smem, const float* src,
                                             uint32_t mbar_addr) {
    asm volatile("mbarrier.arrive.expect_tx.shared.b64 _, [%0], %1;"
                 :: "r"(mbar_addr), "r"(ROW_BYTES) : "memory");
    asm volatile("cp.async.bulk.shared::cluster.global.mbarrier::complete_tx::bytes "
                 "[%0], [%1], %2, [%3];"
                 :: "r"(dst_smem), "l"(src), "r"(ROW_BYTES), "r"(mbar_addr)
                 : "memory");
}

__global__ __launch_bounds__(TPB)
void stats_quant_kernel(const float* __restrict__ w,
                        const float* __restrict__ clip_val,
                        float* __restrict__ out) {
    extern __shared__ char smem[];
    float4* buf[2] = { reinterpret_cast<float4*>(smem),
                       reinterpret_cast<float4*>(smem + ROW_BYTES) };
    uint32_t smem_base = (uint32_t)__cvta_generic_to_shared(smem);
    uint32_t buf_addr[2] = { smem_base, smem_base + ROW_BYTES };
    uint32_t mbar_addr[2] = { smem_base + 65536, smem_base + 65544 };
    float* warp_sums = reinterpret_cast<float*>(smem + 65552);
    float* s_scale_p = reinterpret_cast<float*>(smem + 65584);

    const float hc = 0.5f * clip_val[0];
    const float lo = -hc;
    const float hi = hc - 1e-6f;

    // ---- init mbarriers ----
    if (threadIdx.x == 0) {
        asm volatile("mbarrier.init.shared.b64 [%0], %1;"
                     :: "r"(mbar_addr[0]), "r"(1) : "memory");
        asm volatile("mbarrier.init.shared.b64 [%0], %1;"
                     :: "r"(mbar_addr[1]), "r"(1) : "memory");
        asm volatile("fence.proxy.async.shared::cta;" ::: "memory");
    }
    __syncthreads();

    uint32_t parity[2] = { 0, 0 };

    // rows handled by this CTA: blockIdx.x, +GRID, +2*GRID, ...
    const int row0 = blockIdx.x;

    // ---- prologue: prefetch first row into buf0 ----
    if (row0 < ROWS && threadIdx.x == 0)
        tma_load_row(buf_addr[0], w + (size_t)row0 * COLS, mbar_addr[0]);

    int b = 0;
    for (int row = row0; row < ROWS; row += GRID, b ^= 1) {
        // ---- prefetch next row into the other buffer ----
        // (safe: loop-end __syncthreads of the previous iteration guarantees
        //  that buffer's consumers are done)
        const int nrow = row + GRID;
        if (nrow < ROWS && threadIdx.x == 0)
            tma_load_row(buf_addr[b ^ 1], w + (size_t)nrow * COLS, mbar_addr[b ^ 1]);

        // ---- wait for this row's data ----
        mbar_wait(mbar_addr[b], parity[b]);
        parity[b] ^= 1;

        const float4* __restrict__ srow = buf[b];

        // ---- pass 1: |w| row sum ----
        float asum = 0.0f;
#pragma unroll
        for (int i = 0; i < V4; i++) {
            float4 t = srow[threadIdx.x + i * TPB];
            asum += fabsf(t.x) + fabsf(t.y) + fabsf(t.z) + fabsf(t.w);
        }
#pragma unroll
        for (int off = 16; off > 0; off >>= 1)
            asum += __shfl_xor_sync(0xffffffffu, asum, off);
        if ((threadIdx.x & 31) == 0)
            warp_sums[threadIdx.x >> 5] = asum;
        __syncthreads();
        if (threadIdx.x == 0) {
            float t = 0.0f;
#pragma unroll
            for (int i = 0; i < TPB / 32; i++) t += warp_sums[i];
            *s_scale_p = t * (1.0f / 4096.0f);   // s = 2*mean(|w|) = t/4096
        }
        __syncthreads();

        const float s     = *s_scale_p;
        const float invs  = 1.0f / s;
        const float sdiv8 = s * 0.125f;

        float4* __restrict__ orow =
            reinterpret_cast<float4*>(out + (size_t)row * COLS);

        // ---- pass 2: quantize from smem, stream out ----
#pragma unroll
        for (int i = 0; i < V4; i++) {
            const int idx = threadIdx.x + i * TPB;
            float4 v = srow[idx];
            float4 r;
            float* pv = &v.x;
            float* pr = &r.x;
#pragma unroll
            for (int j = 0; j < 4; j++) {
                float c  = fminf(fmaxf(pv[j] * invs, lo), hi);
                float b4 = fmaf(c, 8.0f, -0.5f);
                pr[j]    = (rintf(b4) + 0.5f) * sdiv8;
            }
            __stcs(&orow[idx], r);
        }

        // ---- mark this buffer consumed (gates the i+2 prefetch) ----
        __syncthreads();
    }
}

extern "C" void kernel_launch(void* const* d_in, const int* in_sizes, int n_in,
                              void* d_out, int out_size) {
    const float* weight   = (const float*)d_in[0];
    const float* clip_val = (const float*)d_in[1];
    float* out            = (float*)d_out;
    (void)in_sizes; (void)n_in; (void)out_size;

    static bool attr_set = false;
    if (!attr_set) {
        cudaFuncSetAttribute(stats_quant_kernel,
                             cudaFuncAttributeMaxDynamicSharedMemorySize,
                             SMEM_BYTES);
        attr_set = true;
    }
    stats_quant_kernel<<<GRID, TPB, SMEM_BYTES>>>(weight, clip_val, out);
}

// round 7
// speedup vs baseline: 1.0166x; 1.0166x over previous
#include <cuda_runtime.h>

// StatsQuantizer 4-bit fake-quant, 8192x8192 fp32.
// Forward math (gradient-only terms eliminated):
//   s    = 2 * mean(|w_row|)          (per row, axis=1)
//   c    = clamp(w/s, -clip/2, clip/2 - 1e-6)
//   out  = s * ((rint(c*8 - 0.5) + 0.5) / 8)
//
// R2 champion shape (one CTA/row, LDG.128 MLP=8 streamed to smem,
// streaming cache hints) with the register-file occupancy limiter
// released: launch_bounds(256,6) caps regs at 42 so BOTH regs and smem
// allow 6 CTAs/SM (R2 was reg-capped at 5). Payload never lives in
// registers, so the cap is spill-free.

#define ROWS 8192
#define COLS 8192
#define TPB  256
#define V4_PER_THREAD (COLS / 4 / TPB)   // 8 float4 per thread

__global__ __launch_bounds__(TPB, 6)
void stats_quant_kernel(const float* __restrict__ w,
                        const float* __restrict__ clip_val,
                        float* __restrict__ out) {
    __shared__ float4 srow[COLS / 4];        // 32 KB
    __shared__ float warp_sums[TPB / 32];
    __shared__ float s_scale;

    const int tid = threadIdx.x;
    const float4* __restrict__ wrow =
        reinterpret_cast<const float4*>(w + (size_t)blockIdx.x * COLS) + tid;
    float4* __restrict__ orow =
        reinterpret_cast<float4*>(out + (size_t)blockIdx.x * COLS) + tid;
    float4* __restrict__ sp = srow + tid;

    // ---- Stream row global -> smem, accumulate |w| on the fly ----
    float asum = 0.0f;
#pragma unroll
    for (int i = 0; i < V4_PER_THREAD; i++) {
        float4 v = __ldcs(wrow + i * TPB);   // evict-first: no reuse
        sp[i * TPB] = v;
        asum += fabsf(v.x) + fabsf(v.y) + fabsf(v.z) + fabsf(v.w);
    }

    // ---- Block reduction: warp shfl, then warp 0 finishes ----
#pragma unroll
    for (int off = 16; off > 0; off >>= 1)
        asum += __shfl_xor_sync(0xffffffffu, asum, off);
    if ((tid & 31) == 0)
        warp_sums[tid >> 5] = asum;
    __syncthreads();
    if (tid < 32) {
        float t = (tid < TPB / 32) ? warp_sums[tid] : 0.0f;
#pragma unroll
        for (int off = 4; off > 0; off >>= 1)
            t += __shfl_xor_sync(0xffffffffu, t, off);
        if (tid == 0)
            s_scale = t * (1.0f / 4096.0f);  // s = 2*mean(|w|) = t/4096
    }
    __syncthreads();

    const float s     = s_scale;
    const float invs  = 1.0f / s;
    const float hc    = 0.5f * clip_val[0];
    const float lo    = -hc;
    const float hi    = hc - 1e-6f;
    const float sdiv8 = s * 0.125f;

    // ---- Quantize from smem, stream out ----
#pragma unroll
    for (int i = 0; i < V4_PER_THREAD; i++) {
        float4 v = sp[i * TPB];
        float4 r;
        float* pv = &v.x;
        float* pr = &r.x;
#pragma unroll
        for (int j = 0; j < 4; j++) {
            float c  = fminf(fmaxf(pv[j] * invs, lo), hi);
            float b4 = fmaf(c, 8.0f, -0.5f);
            pr[j]    = (rintf(b4) + 0.5f) * sdiv8;
        }
        __stcs(orow + i * TPB, r);           // evict-first store
    }
}

extern "C" void kernel_launch(void* const* d_in, const int* in_sizes, int n_in,
                              void* d_out, int out_size) {
    const float* weight   = (const float*)d_in[0];
    const float* clip_val = (const float*)d_in[1];
    float* out            = (float*)d_out;
    (void)in_sizes; (void)n_in; (void)out_size;

    stats_quant_kernel<<<ROWS, TPB>>>(weight, clip_val, out);
}